// round 5
// baseline (speedup 1.0000x reference)
#include <cuda_runtime.h>

#define N_NODES 8192
#define N_EDGES 16384
#define E4      (N_EDGES / 4)      // 4096 float4 per matrix row
#define NCHUNK  32
#define ROWS_PB (N_NODES / NCHUNK) // 256 rows per gather block
#define K1_THREADS 128

// ---------------- scratch (device globals; no allocs allowed) ----------------
// Partial column-reductions: [NCHUNK][E4][4 float4] = 8 MB each. Fully
// overwritten every launch -> deterministic, no zeroing needed.
__device__ __align__(16) float4 g_pbo[(size_t)NCHUNK * E4 * 4];
__device__ __align__(16) float4 g_pbi[(size_t)NCHUNK * E4 * 4];
__device__ __align__(16) float  g_so[N_EDGES];
__device__ __align__(16) float  g_si[N_EDGES];

#define FMA4(acc, s, v) \
    acc.x += (s) * (v).x; acc.y += (s) * (v).y; \
    acc.z += (s) * (v).z; acc.w += (s) * (v).w;

__device__ __forceinline__ float4 ldcs4(const float4* p) {
    return __ldcs(p);   // streaming: single-use data, evict-first in L2
}

// ---------------- kernel 1: partial column reductions -------------------------
// Grid: (E4/128 = 32, NCHUNK = 32, 2). z=0 handles Ro -> pbo, z=1 Ri -> pbi.
// Each thread owns 4 consecutive edges (one float4 per row), accumulates a
// 4x4 outer-product partial over its 256-row chunk in 16 registers, stores
// with plain STG.128. Split along z halves regs/thread -> ~70% occupancy.
__global__ __launch_bounds__(K1_THREADS)
void gather_kernel(const float4* __restrict__ X4,
                   const float4* __restrict__ Ri4,
                   const float4* __restrict__ Ro4) {
    __shared__ float4 sX[ROWS_PB];   // 4 KB
    const int n0 = blockIdx.y * ROWS_PB;
    for (int i = threadIdx.x; i < ROWS_PB; i += K1_THREADS)
        sX[i] = X4[n0 + i];
    __syncthreads();

    const float4* R = (blockIdx.z == 0) ? Ro4 : Ri4;
    float4* P = (blockIdx.z == 0) ? g_pbo : g_pbi;

    const int e4 = blockIdx.x * K1_THREADS + threadIdx.x;
    const float4* r = R + (size_t)n0 * E4 + e4;

    float4 z = make_float4(0.f, 0.f, 0.f, 0.f);
    float4 a0 = z, a1 = z, a2 = z, a3 = z;

    #pragma unroll 8
    for (int nl = 0; nl < ROWS_PB; ++nl) {
        float4 v = ldcs4(r + (size_t)nl * E4);
        float4 x = sX[nl];
        FMA4(a0, v.x, x); FMA4(a1, v.y, x); FMA4(a2, v.z, x); FMA4(a3, v.w, x);
    }

    float4* p = P + ((size_t)blockIdx.y * E4 + e4) * 4;
    p[0] = a0; p[1] = a1; p[2] = a2; p[3] = a3;
}

// ---------------- kernel 2: reduce partials, compute so/si --------------------
__global__ __launch_bounds__(256)
void edge_kernel(const float* __restrict__ ew,
                 const float* __restrict__ kern) {
    int e = blockIdx.x * blockDim.x + threadIdx.x;
    if (e >= N_EDGES) return;
    const int base = e >> 2;
    const int j = e & 3;

    float4 bo = make_float4(0.f, 0.f, 0.f, 0.f);
    float4 bi = make_float4(0.f, 0.f, 0.f, 0.f);
    #pragma unroll 8
    for (int c = 0; c < NCHUNK; ++c) {
        float4 p = g_pbo[((size_t)c * E4 + base) * 4 + j];
        bo.x += p.x; bo.y += p.y; bo.z += p.z; bo.w += p.w;
        float4 q = g_pbi[((size_t)c * E4 + base) * 4 + j];
        bi.x += q.x; bi.y += q.y; bi.z += q.z; bi.w += q.w;
    }

    float w = ew[e];
    g_so[e] = w * (bo.x * kern[0] + bo.y * kern[1] + bo.z * kern[2] + bo.w * kern[3]);
    g_si[e] = w * (bi.x * kern[4] + bi.y * kern[5] + bi.z * kern[6] + bi.w * kern[7]);
}

// ---------------- kernel 3: out[n] = Ri[n,:]·so + Ro[n,:]·si + X[n]·k[8:12] --
__global__ __launch_bounds__(256)
void scatter_kernel(const float4* __restrict__ Ri4,
                    const float4* __restrict__ Ro4,
                    const float4* __restrict__ X4,
                    const float* __restrict__ kern,
                    float* __restrict__ out) {
    const int n = blockIdx.x;
    const float4* ri = Ri4 + (size_t)n * E4;
    const float4* ro = Ro4 + (size_t)n * E4;
    const float4* so4 = reinterpret_cast<const float4*>(g_so);
    const float4* si4 = reinterpret_cast<const float4*>(g_si);

    float s = 0.0f;
    #pragma unroll 4
    for (int t = 0; t < E4 / 256; ++t) {
        int j = t * 256 + threadIdx.x;
        float4 a = __ldcs(ri + j), w = so4[j];
        s += a.x * w.x + a.y * w.y + a.z * w.z + a.w * w.w;
        float4 b = __ldcs(ro + j), v = si4[j];
        s += b.x * v.x + b.y * v.y + b.z * v.z + b.w * v.w;
    }

    #pragma unroll
    for (int off = 16; off > 0; off >>= 1)
        s += __shfl_down_sync(0xFFFFFFFFu, s, off);

    __shared__ float red[8];
    int wid = threadIdx.x >> 5, lid = threadIdx.x & 31;
    if (lid == 0) red[wid] = s;
    __syncthreads();
    if (wid == 0) {
        s = (lid < 8) ? red[lid] : 0.0f;
        #pragma unroll
        for (int off = 4; off > 0; off >>= 1)
            s += __shfl_down_sync(0xFFFFFFFFu, s, off);
        if (lid == 0) {
            float4 x = X4[n];
            s += x.x * kern[8] + x.y * kern[9] + x.z * kern[10] + x.w * kern[11];
            out[n] = s;
        }
    }
}

// ---------------- launch ------------------------------------------------------
extern "C" void kernel_launch(void* const* d_in, const int* in_sizes, int n_in,
                              void* d_out, int out_size) {
    const float* X    = (const float*)d_in[0];   // [8192, 4]
    const float* e    = (const float*)d_in[1];   // [16384, 1]
    const float* Ri   = (const float*)d_in[2];   // [8192, 16384]
    const float* Ro   = (const float*)d_in[3];   // [8192, 16384]
    const float* kern = (const float*)d_in[4];   // [12, 1]
    float* out = (float*)d_out;                  // [8192, 1]

    gather_kernel<<<dim3(E4 / K1_THREADS, NCHUNK, 2), K1_THREADS>>>(
        (const float4*)X, (const float4*)Ri, (const float4*)Ro);
    edge_kernel<<<(N_EDGES + 255) / 256, 256>>>(e, kern);
    scatter_kernel<<<N_NODES, 256>>>(
        (const float4*)Ri, (const float4*)Ro, (const float4*)X, kern, out);
}

// round 8
// speedup vs baseline: 1.0540x; 1.0540x over previous
#include <cuda_runtime.h>

#define N_NODES 8192
#define N_EDGES 16384
#define E4      (N_EDGES / 4)      // 4096 float4 per matrix row
#define NCHUNK  64
#define ROWS_PB (N_NODES / NCHUNK) // 128 rows per gather block
#define K1_THREADS 128

// ---------------- scratch (device globals; no allocs allowed) ----------------
// Partial column-reductions: [NCHUNK][E4][4 float4] = 16 MB each. Fully
// overwritten every launch -> deterministic, no zeroing needed.
__device__ __align__(16) float4 g_pbo[(size_t)NCHUNK * E4 * 4];
__device__ __align__(16) float4 g_pbi[(size_t)NCHUNK * E4 * 4];
__device__ __align__(16) float  g_so[N_EDGES];
__device__ __align__(16) float  g_si[N_EDGES];

#define FMA4(acc, s, v) \
    acc.x += (s) * (v).x; acc.y += (s) * (v).y; \
    acc.z += (s) * (v).z; acc.w += (s) * (v).w;

// ---------------- kernel 1: partial bo = Ro^T X, bi = Ri^T X ------------------
// Grid: (E4/128 = 32, NCHUNK = 64) = 2048 blocks (~13.8/SM, occ ~85%).
// Combined Ri+Ro: 2 independent LDG.128 per loop iter -> high per-warp MLP.
// Each thread owns 4 consecutive edges, accumulates 4x4 outer-product
// partials over its 128-row chunk in 32 registers, stores with STG.128.
__global__ __launch_bounds__(K1_THREADS)
void gather_kernel(const float4* __restrict__ X4,
                   const float4* __restrict__ Ri4,
                   const float4* __restrict__ Ro4) {
    __shared__ float4 sX[ROWS_PB];   // 2 KB
    const int n0 = blockIdx.y * ROWS_PB;
    for (int i = threadIdx.x; i < ROWS_PB; i += K1_THREADS)
        sX[i] = X4[n0 + i];
    __syncthreads();

    const int e4 = blockIdx.x * K1_THREADS + threadIdx.x;
    const float4* ro = Ro4 + (size_t)n0 * E4 + e4;
    const float4* ri = Ri4 + (size_t)n0 * E4 + e4;

    float4 z = make_float4(0.f, 0.f, 0.f, 0.f);
    float4 o0 = z, o1 = z, o2 = z, o3 = z;
    float4 i0 = z, i1 = z, i2 = z, i3 = z;

    #pragma unroll 8
    for (int nl = 0; nl < ROWS_PB; ++nl) {
        float4 x = sX[nl];
        float4 r = ro[(size_t)nl * E4];
        float4 q = ri[(size_t)nl * E4];
        FMA4(o0, r.x, x); FMA4(o1, r.y, x); FMA4(o2, r.z, x); FMA4(o3, r.w, x);
        FMA4(i0, q.x, x); FMA4(i1, q.y, x); FMA4(i2, q.z, x); FMA4(i3, q.w, x);
    }

    float4* pbo = g_pbo + ((size_t)blockIdx.y * E4 + e4) * 4;
    float4* pbi = g_pbi + ((size_t)blockIdx.y * E4 + e4) * 4;
    pbo[0] = o0; pbo[1] = o1; pbo[2] = o2; pbo[3] = o3;
    pbi[0] = i0; pbi[1] = i1; pbi[2] = i2; pbi[3] = i3;
}

// ---------------- kernel 2: reduce partials, compute so/si --------------------
__global__ __launch_bounds__(256)
void edge_kernel(const float* __restrict__ ew,
                 const float* __restrict__ kern) {
    int e = blockIdx.x * blockDim.x + threadIdx.x;
    if (e >= N_EDGES) return;
    const int base = e >> 2;
    const int j = e & 3;

    float4 bo = make_float4(0.f, 0.f, 0.f, 0.f);
    float4 bi = make_float4(0.f, 0.f, 0.f, 0.f);
    #pragma unroll 8
    for (int c = 0; c < NCHUNK; ++c) {
        float4 p = g_pbo[((size_t)c * E4 + base) * 4 + j];
        bo.x += p.x; bo.y += p.y; bo.z += p.z; bo.w += p.w;
        float4 q = g_pbi[((size_t)c * E4 + base) * 4 + j];
        bi.x += q.x; bi.y += q.y; bi.z += q.z; bi.w += q.w;
    }

    float w = ew[e];
    g_so[e] = w * (bo.x * kern[0] + bo.y * kern[1] + bo.z * kern[2] + bo.w * kern[3]);
    g_si[e] = w * (bi.x * kern[4] + bi.y * kern[5] + bi.z * kern[6] + bi.w * kern[7]);
}

// ---------------- kernel 3: out[n] = Ri[n,:]·so + Ro[n,:]·si + X[n]·k[8:12] --
__global__ __launch_bounds__(256)
void scatter_kernel(const float4* __restrict__ Ri4,
                    const float4* __restrict__ Ro4,
                    const float4* __restrict__ X4,
                    const float* __restrict__ kern,
                    float* __restrict__ out) {
    const int n = blockIdx.x;
    const float4* ri = Ri4 + (size_t)n * E4;
    const float4* ro = Ro4 + (size_t)n * E4;
    const float4* so4 = reinterpret_cast<const float4*>(g_so);
    const float4* si4 = reinterpret_cast<const float4*>(g_si);

    float s = 0.0f;
    #pragma unroll 4
    for (int t = 0; t < E4 / 256; ++t) {
        int j = t * 256 + threadIdx.x;
        float4 a = ri[j], w = so4[j];
        s += a.x * w.x + a.y * w.y + a.z * w.z + a.w * w.w;
        float4 b = ro[j], v = si4[j];
        s += b.x * v.x + b.y * v.y + b.z * v.z + b.w * v.w;
    }

    #pragma unroll
    for (int off = 16; off > 0; off >>= 1)
        s += __shfl_down_sync(0xFFFFFFFFu, s, off);

    __shared__ float red[8];
    int wid = threadIdx.x >> 5, lid = threadIdx.x & 31;
    if (lid == 0) red[wid] = s;
    __syncthreads();
    if (wid == 0) {
        s = (lid < 8) ? red[lid] : 0.0f;
        #pragma unroll
        for (int off = 4; off > 0; off >>= 1)
            s += __shfl_down_sync(0xFFFFFFFFu, s, off);
        if (lid == 0) {
            float4 x = X4[n];
            s += x.x * kern[8] + x.y * kern[9] + x.z * kern[10] + x.w * kern[11];
            out[n] = s;
        }
    }
}

// ---------------- launch ------------------------------------------------------
extern "C" void kernel_launch(void* const* d_in, const int* in_sizes, int n_in,
                              void* d_out, int out_size) {
    const float* X    = (const float*)d_in[0];   // [8192, 4]
    const float* e    = (const float*)d_in[1];   // [16384, 1]
    const float* Ri   = (const float*)d_in[2];   // [8192, 16384]
    const float* Ro   = (const float*)d_in[3];   // [8192, 16384]
    const float* kern = (const float*)d_in[4];   // [12, 1]
    float* out = (float*)d_out;                  // [8192, 1]

    gather_kernel<<<dim3(E4 / K1_THREADS, NCHUNK), K1_THREADS>>>(
        (const float4*)X, (const float4*)Ri, (const float4*)Ro);
    edge_kernel<<<(N_EDGES + 255) / 256, 256>>>(e, kern);
    scatter_kernel<<<N_NODES, 256>>>(
        (const float4*)Ri, (const float4*)Ro, (const float4*)X, kern, out);
}

// round 10
// speedup vs baseline: 1.0932x; 1.0372x over previous
#include <cuda_runtime.h>
#include <cstdint>

#define N_NODES 8192
#define N_EDGES 16384
#define E4      (N_EDGES / 4)      // 4096 float4 per matrix row
#define NCHUNK  64
#define ROWS_PB (N_NODES / NCHUNK) // 128 rows per gather block
#define TB      2                  // rows per pipeline stage
#define NT      (ROWS_PB / TB)     // 64 stages
#define DEPTH   3                  // cp.async pipeline depth
#define K1_THREADS 128

// ---------------- scratch (device globals; no allocs allowed) ----------------
// Partial column-reductions: [NCHUNK][E4][4 float4] = 16 MB each. Fully
// overwritten every launch -> deterministic, no zeroing needed.
__device__ __align__(16) float4 g_pbo[(size_t)NCHUNK * E4 * 4];
__device__ __align__(16) float4 g_pbi[(size_t)NCHUNK * E4 * 4];
__device__ __align__(16) float  g_so[N_EDGES];
__device__ __align__(16) float  g_si[N_EDGES];

#define FMA4(acc, s, v) \
    acc.x += (s) * (v).x; acc.y += (s) * (v).y; \
    acc.z += (s) * (v).z; acc.w += (s) * (v).w;

__device__ __forceinline__ void cp_async16(uint32_t dst, const void* src) {
    asm volatile("cp.async.cg.shared.global [%0], [%1], 16;\n"
                 :: "r"(dst), "l"(src));
}
__device__ __forceinline__ void cp_commit() {
    asm volatile("cp.async.commit_group;\n");
}
template <int N>
__device__ __forceinline__ void cp_wait() {
    asm volatile("cp.async.wait_group %0;\n" :: "n"(N));
}

// ---------------- kernel 1: partial bo = Ro^T X, bi = Ri^T X ------------------
// cp.async staging: load depth decoupled from registers. Each thread owns 4
// consecutive edges; per stage, TB rows of both matrices land in smem via
// LDGSTS (no data registers), then 32 FMAs/row from LDS. 2 pending groups x
// 2KB/warp x ~32 warps/SM = ~128KB outstanding -> HBM pinned.
__global__ __launch_bounds__(K1_THREADS)
void gather_kernel(const float4* __restrict__ X4,
                   const float4* __restrict__ Ri4,
                   const float4* __restrict__ Ro4) {
    __shared__ float4 sX[ROWS_PB];                         // 2 KB
    __shared__ float4 tile[DEPTH][2][TB][K1_THREADS];      // 24 KB

    const int n0 = blockIdx.y * ROWS_PB;
    for (int i = threadIdx.x; i < ROWS_PB; i += K1_THREADS)
        sX[i] = X4[n0 + i];

    const int e4 = blockIdx.x * K1_THREADS + threadIdx.x;
    const float4* ro = Ro4 + (size_t)n0 * E4 + e4;
    const float4* ri = Ri4 + (size_t)n0 * E4 + e4;

    const uint32_t ROWSTR = K1_THREADS * 16;       // bytes per tile row
    const uint32_t MATSTR = TB * ROWSTR;           // bytes per matrix slot
    const uint32_t BUFSTR = 2 * MATSTR;            // bytes per buffer
    const uint32_t tbase =
        (uint32_t)__cvta_generic_to_shared(&tile[0][0][0][threadIdx.x]);

    auto fill = [&](int buf, int t) {
        uint32_t b = tbase + (uint32_t)buf * BUFSTR;
        #pragma unroll
        for (int r = 0; r < TB; ++r) {
            size_t off = (size_t)(t * TB + r) * E4;
            cp_async16(b + r * ROWSTR,          ro + off);
            cp_async16(b + MATSTR + r * ROWSTR, ri + off);
        }
        cp_commit();
    };

    fill(0, 0);
    fill(1, 1);

    float4 z = make_float4(0.f, 0.f, 0.f, 0.f);
    float4 o0 = z, o1 = z, o2 = z, o3 = z;
    float4 i0 = z, i1 = z, i2 = z, i3 = z;

    __syncthreads();   // sX visible

    for (int t = 0; t < NT; ++t) {
        const int buf = t % DEPTH;
        if (t + 2 < NT) {
            fill((t + 2) % DEPTH, t + 2);
            cp_wait<2>();            // group t complete (t+1, t+2 in flight)
        } else {
            cp_wait<0>();
        }
        __syncthreads();             // stage t visible to all threads
        #pragma unroll
        for (int r = 0; r < TB; ++r) {
            float4 x = sX[t * TB + r];
            float4 v = tile[buf][0][r][threadIdx.x];
            float4 q = tile[buf][1][r][threadIdx.x];
            FMA4(o0, v.x, x); FMA4(o1, v.y, x); FMA4(o2, v.z, x); FMA4(o3, v.w, x);
            FMA4(i0, q.x, x); FMA4(i1, q.y, x); FMA4(i2, q.z, x); FMA4(i3, q.w, x);
        }
        __syncthreads();             // buffer free for refill
    }

    float4* pbo = g_pbo + ((size_t)blockIdx.y * E4 + e4) * 4;
    float4* pbi = g_pbi + ((size_t)blockIdx.y * E4 + e4) * 4;
    pbo[0] = o0; pbo[1] = o1; pbo[2] = o2; pbo[3] = o3;
    pbi[0] = i0; pbi[1] = i1; pbi[2] = i2; pbi[3] = i3;
}

// ---------------- kernel 2: reduce partials, compute so/si --------------------
__global__ __launch_bounds__(256)
void edge_kernel(const float* __restrict__ ew,
                 const float* __restrict__ kern) {
    int e = blockIdx.x * blockDim.x + threadIdx.x;
    if (e >= N_EDGES) return;
    const int base = e >> 2;
    const int j = e & 3;

    float4 bo = make_float4(0.f, 0.f, 0.f, 0.f);
    float4 bi = make_float4(0.f, 0.f, 0.f, 0.f);
    #pragma unroll 8
    for (int c = 0; c < NCHUNK; ++c) {
        float4 p = g_pbo[((size_t)c * E4 + base) * 4 + j];
        bo.x += p.x; bo.y += p.y; bo.z += p.z; bo.w += p.w;
        float4 q = g_pbi[((size_t)c * E4 + base) * 4 + j];
        bi.x += q.x; bi.y += q.y; bi.z += q.z; bi.w += q.w;
    }

    float w = ew[e];
    g_so[e] = w * (bo.x * kern[0] + bo.y * kern[1] + bo.z * kern[2] + bo.w * kern[3]);
    g_si[e] = w * (bi.x * kern[4] + bi.y * kern[5] + bi.z * kern[6] + bi.w * kern[7]);
}

// ---------------- kernel 3: out[n] = Ri[n,:]·so + Ro[n,:]·si + X[n]·k[8:12] --
__global__ __launch_bounds__(256)
void scatter_kernel(const float4* __restrict__ Ri4,
                    const float4* __restrict__ Ro4,
                    const float4* __restrict__ X4,
                    const float* __restrict__ kern,
                    float* __restrict__ out) {
    const int n = blockIdx.x;
    const float4* ri = Ri4 + (size_t)n * E4;
    const float4* ro = Ro4 + (size_t)n * E4;
    const float4* so4 = reinterpret_cast<const float4*>(g_so);
    const float4* si4 = reinterpret_cast<const float4*>(g_si);

    float s = 0.0f;
    #pragma unroll 4
    for (int t = 0; t < E4 / 256; ++t) {
        int j = t * 256 + threadIdx.x;
        float4 a = ri[j], w = so4[j];
        s += a.x * w.x + a.y * w.y + a.z * w.z + a.w * w.w;
        float4 b = ro[j], v = si4[j];
        s += b.x * v.x + b.y * v.y + b.z * v.z + b.w * v.w;
    }

    #pragma unroll
    for (int off = 16; off > 0; off >>= 1)
        s += __shfl_down_sync(0xFFFFFFFFu, s, off);

    __shared__ float red[8];
    int wid = threadIdx.x >> 5, lid = threadIdx.x & 31;
    if (lid == 0) red[wid] = s;
    __syncthreads();
    if (wid == 0) {
        s = (lid < 8) ? red[lid] : 0.0f;
        #pragma unroll
        for (int off = 4; off > 0; off >>= 1)
            s += __shfl_down_sync(0xFFFFFFFFu, s, off);
        if (lid == 0) {
            float4 x = X4[n];
            s += x.x * kern[8] + x.y * kern[9] + x.z * kern[10] + x.w * kern[11];
            out[n] = s;
        }
    }
}

// ---------------- launch ------------------------------------------------------
extern "C" void kernel_launch(void* const* d_in, const int* in_sizes, int n_in,
                              void* d_out, int out_size) {
    const float* X    = (const float*)d_in[0];   // [8192, 4]
    const float* e    = (const float*)d_in[1];   // [16384, 1]
    const float* Ri   = (const float*)d_in[2];   // [8192, 16384]
    const float* Ro   = (const float*)d_in[3];   // [8192, 16384]
    const float* kern = (const float*)d_in[4];   // [12, 1]
    float* out = (float*)d_out;                  // [8192, 1]

    gather_kernel<<<dim3(E4 / K1_THREADS, NCHUNK), K1_THREADS>>>(
        (const float4*)X, (const float4*)Ri, (const float4*)Ro);
    edge_kernel<<<(N_EDGES + 255) / 256, 256>>>(e, kern);
    scatter_kernel<<<N_NODES, 256>>>(
        (const float4*)Ri, (const float4*)Ro, (const float4*)X, kern, out);
}